// round 3
// baseline (speedup 1.0000x reference)
#include <cuda_runtime.h>
#include <cuda_bf16.h>
#include <math.h>

#define N_NODES 50000
#define N_EDGES 800000
#define LN_EPS 1e-5f

// ---------------- scratch (no allocations allowed -> device globals) ----------
__device__ int   g_is64;
__device__ int   g_cnt[N_NODES];
__device__ int   g_cursor[N_NODES];
__device__ int   g_rowptr[N_NODES + 1];
__device__ int   g_cntrel[N_NODES * 2];
__device__ float g_invcnt[N_NODES * 2];
__device__ int   g_epack[N_EDGES];              // (src<<1)|rel, CSR-ordered by dst
__device__ float g_proj1[N_NODES * 128];        // [n][r*64+c]  x@W1[r]
__device__ float g_sel1 [N_NODES * 64];         // x@root1 + b1
__device__ float g_h    [N_NODES * 64];         // layer1 output
__device__ float g_proj2[N_NODES * 128];
__device__ float g_sel2 [N_NODES * 64];

// ---------------- dtype sniff: int64 edge_index has zero high words -----------
__global__ void sniff_kernel(const int* __restrict__ ei32) {
    __shared__ int acc[256];
    int t = threadIdx.x;
    int v = 0;
    // sample 2048 odd 32-bit words (= high words if the data is int64)
    for (int i = t; i < 2048; i += 256) v |= ei32[2 * i + 1];
    acc[t] = v;
    __syncthreads();
    for (int off = 128; off; off >>= 1) {
        if (t < off) acc[t] |= acc[t + off];
        __syncthreads();
    }
    if (t == 0) g_is64 = (acc[0] == 0) ? 1 : 0;
}

__device__ __forceinline__ int load_idx(const void* p, int i) {
    int v = g_is64 ? (int)((const long long*)p)[i] : ((const int*)p)[i];
    return v;
}

// ---------------- CSR build ---------------------------------------------------
__global__ void zero_kernel() {
    int i = blockIdx.x * blockDim.x + threadIdx.x;
    if (i < N_NODES) { g_cnt[i] = 0; g_cursor[i] = 0; }
    if (i < 2 * N_NODES) g_cntrel[i] = 0;
}

__global__ void count_kernel(const void* __restrict__ ei,
                             const void* __restrict__ et) {
    int e = blockIdx.x * blockDim.x + threadIdx.x;
    if (e >= N_EDGES) return;
    int d = load_idx(ei, N_EDGES + e);
    int r = load_idx(et, e) & 1;
    d = min(max(d, 0), N_NODES - 1);
    atomicAdd(&g_cnt[d], 1);
    atomicAdd(&g_cntrel[d * 2 + r], 1);
}

__global__ void scan_kernel() {
    __shared__ int ss[1024];
    int t = threadIdx.x;
    const int C = (N_NODES + 1023) / 1024;   // 49
    int beg = t * C;
    int end = min(beg + C, N_NODES);
    int s = 0;
    for (int i = beg; i < end; i++) s += g_cnt[i];
    ss[t] = s;
    __syncthreads();
    for (int off = 1; off < 1024; off <<= 1) {
        int v = (t >= off) ? ss[t - off] : 0;
        __syncthreads();
        ss[t] += v;
        __syncthreads();
    }
    int run = (t == 0) ? 0 : ss[t - 1];
    for (int i = beg; i < end; i++) { g_rowptr[i] = run; run += g_cnt[i]; }
    if (t == 1023) g_rowptr[N_NODES] = ss[1023];
}

__global__ void scatter_kernel(const void* __restrict__ ei,
                               const void* __restrict__ et) {
    int e = blockIdx.x * blockDim.x + threadIdx.x;
    if (e >= N_EDGES) return;
    int s = load_idx(ei, e);
    int d = load_idx(ei, N_EDGES + e);
    int r = load_idx(et, e) & 1;
    s = min(max(s, 0), N_NODES - 1);
    d = min(max(d, 0), N_NODES - 1);
    int pos = g_rowptr[d] + atomicAdd(&g_cursor[d], 1);
    if (pos >= 0 && pos < N_EDGES) g_epack[pos] = (s << 1) | r;
}

__global__ void invcnt_kernel() {
    int i = blockIdx.x * blockDim.x + threadIdx.x;
    if (i < 2 * N_NODES)
        g_invcnt[i] = 1.0f / fmaxf((float)g_cntrel[i], 1.0f);
}

// ---------------- fused GEMM: [N,KD] @ [KD,192] -> sel[N,64], proj[N,128] -----
// cols 0..63 = root (+bias), 64..127 = W[0], 128..191 = W[1]
// 64-row x 192-col block, 256 threads, K staged in 32-slices (static smem, ~32KB).
template <int KD, bool USE_H, bool L2OUT>
__global__ void __launch_bounds__(256)
gemm_kernel(const float* __restrict__ Xin, const float* __restrict__ root,
            const float* __restrict__ W, const float* __restrict__ bias) {
    __shared__ float Ws[32 * 192];
    __shared__ float Xs[64 * 33];
    const float* X = USE_H ? g_h : Xin;
    float* sel  = L2OUT ? g_sel2  : g_sel1;
    float* proj = L2OUT ? g_proj2 : g_proj1;

    const int tid = threadIdx.x;
    const int row0 = blockIdx.x * 64;
    const int tx = tid & 15;     // cols: 2*tx + 32*j (+1)
    const int ty = tid >> 4;     // rows: ty*4 .. ty*4+3

    float acc[4][12];
#pragma unroll
    for (int i = 0; i < 4; i++)
#pragma unroll
        for (int j = 0; j < 12; j++) acc[i][j] = 0.0f;

    for (int k0 = 0; k0 < KD; k0 += 32) {
        __syncthreads();
        for (int idx = tid; idx < 32 * 192; idx += 256) {
            int kk = idx / 192, cc = idx % 192;
            int k = k0 + kk;
            float w;
            if (cc < 64) w = root[k * 64 + cc];
            else         w = W[(((cc >> 6) - 1) * KD + k) * 64 + (cc & 63)];
            Ws[idx] = w;
        }
        for (int idx = tid; idx < 64 * 32; idx += 256) {
            int rw = idx >> 5, kk = idx & 31;
            int n = row0 + rw;
            Xs[rw * 33 + kk] = (n < N_NODES) ? X[n * KD + k0 + kk] : 0.0f;
        }
        __syncthreads();

#pragma unroll 4
        for (int kk = 0; kk < 32; kk++) {
            float xv[4];
#pragma unroll
            for (int i = 0; i < 4; i++) xv[i] = Xs[(ty * 4 + i) * 33 + kk];
#pragma unroll
            for (int j = 0; j < 6; j++) {
                float2 w2 = *reinterpret_cast<const float2*>(&Ws[kk * 192 + 2 * tx + 32 * j]);
#pragma unroll
                for (int i = 0; i < 4; i++) {
                    acc[i][2 * j]     = fmaf(xv[i], w2.x, acc[i][2 * j]);
                    acc[i][2 * j + 1] = fmaf(xv[i], w2.y, acc[i][2 * j + 1]);
                }
            }
        }
    }

#pragma unroll
    for (int i = 0; i < 4; i++) {
        int n = row0 + ty * 4 + i;
        if (n < N_NODES) {
#pragma unroll
            for (int j = 0; j < 6; j++) {
                int cc = 2 * tx + 32 * j;
                float lo = acc[i][2 * j], hi = acc[i][2 * j + 1];
                if (cc < 64) {
                    float2 o; o.x = lo + bias[cc]; o.y = hi + bias[cc + 1];
                    *reinterpret_cast<float2*>(&sel[n * 64 + cc]) = o;
                } else {
                    float2 o; o.x = lo; o.y = hi;
                    *reinterpret_cast<float2*>(&proj[n * 128 + (cc - 64)]) = o;
                }
            }
        }
    }
}

// ---------------- gather + mean + LayerNorm (+GELU) ---------------------------
// One warp per node; lane owns cols {lane, lane+32}.
template <bool DO_GELU, bool L2>
__global__ void gather_kernel(const float* __restrict__ gamma,
                              const float* __restrict__ beta,
                              float* __restrict__ outp) {
    const float* sel  = L2 ? g_sel2  : g_sel1;
    const float* proj = L2 ? g_proj2 : g_proj1;
    float* out = L2 ? outp : g_h;

    int warp = (blockIdx.x * blockDim.x + threadIdx.x) >> 5;
    int lane = threadIdx.x & 31;
    if (warp >= N_NODES) return;
    const int i = warp;
    int beg = g_rowptr[i], end = g_rowptr[i + 1];

    float a00 = 0.f, a01 = 0.f, a10 = 0.f, a11 = 0.f;
    int t = beg;
    for (; t + 4 <= end; t += 4) {
        int e0 = g_epack[t], e1 = g_epack[t + 1], e2 = g_epack[t + 2], e3 = g_epack[t + 3];
        const float* p0 = proj + (e0 >> 1) * 128 + ((e0 & 1) << 6);
        const float* p1 = proj + (e1 >> 1) * 128 + ((e1 & 1) << 6);
        const float* p2 = proj + (e2 >> 1) * 128 + ((e2 & 1) << 6);
        const float* p3 = proj + (e3 >> 1) * 128 + ((e3 & 1) << 6);
        float v00 = p0[lane], v01 = p0[lane + 32];
        float v10 = p1[lane], v11 = p1[lane + 32];
        float v20 = p2[lane], v21 = p2[lane + 32];
        float v30 = p3[lane], v31 = p3[lane + 32];
        if (e0 & 1) { a10 += v00; a11 += v01; } else { a00 += v00; a01 += v01; }
        if (e1 & 1) { a10 += v10; a11 += v11; } else { a00 += v10; a01 += v11; }
        if (e2 & 1) { a10 += v20; a11 += v21; } else { a00 += v20; a01 += v21; }
        if (e3 & 1) { a10 += v30; a11 += v31; } else { a00 += v30; a01 += v31; }
    }
    for (; t < end; t++) {
        int e0 = g_epack[t];
        const float* p0 = proj + (e0 >> 1) * 128 + ((e0 & 1) << 6);
        float v00 = p0[lane], v01 = p0[lane + 32];
        if (e0 & 1) { a10 += v00; a11 += v01; } else { a00 += v00; a01 += v01; }
    }

    float ic0 = g_invcnt[2 * i], ic1 = g_invcnt[2 * i + 1];
    float v0 = sel[i * 64 + lane]      + a00 * ic0 + a10 * ic1;
    float v1 = sel[i * 64 + lane + 32] + a01 * ic0 + a11 * ic1;

    float s  = v0 + v1;
    float sq = v0 * v0 + v1 * v1;
#pragma unroll
    for (int off = 16; off; off >>= 1) {
        s  += __shfl_xor_sync(0xffffffffu, s,  off);
        sq += __shfl_xor_sync(0xffffffffu, sq, off);
    }
    float mean = s * (1.0f / 64.0f);
    float var  = sq * (1.0f / 64.0f) - mean * mean;
    float inv  = rsqrtf(var + LN_EPS);
    v0 = (v0 - mean) * inv * gamma[lane]      + beta[lane];
    v1 = (v1 - mean) * inv * gamma[lane + 32] + beta[lane + 32];

    if (DO_GELU) {
        v0 = 0.5f * v0 * (1.0f + erff(v0 * 0.70710678118654752440f));
        v1 = 0.5f * v1 * (1.0f + erff(v1 * 0.70710678118654752440f));
    }
    out[i * 64 + lane]      = v0;
    out[i * 64 + lane + 32] = v1;
}

// ---------------- launcher ----------------------------------------------------
extern "C" void kernel_launch(void* const* d_in, const int* in_sizes, int n_in,
                              void* d_out, int out_size) {
    const float* x     = (const float*)d_in[0];
    const void*  ei    = d_in[1];
    const void*  et    = d_in[2];
    const float* W1    = (const float*)d_in[3];
    const float* root1 = (const float*)d_in[4];
    const float* b1    = (const float*)d_in[5];
    const float* g1    = (const float*)d_in[6];
    const float* be1   = (const float*)d_in[7];
    const float* W2    = (const float*)d_in[8];
    const float* root2 = (const float*)d_in[9];
    const float* b2    = (const float*)d_in[10];
    const float* g2    = (const float*)d_in[11];
    const float* be2   = (const float*)d_in[12];
    float* out = (float*)d_out;

    // ---- dtype sniff + CSR build (by dst) ----
    sniff_kernel<<<1, 256>>>((const int*)ei);
    zero_kernel<<<(2 * N_NODES + 255) / 256, 256>>>();
    count_kernel<<<(N_EDGES + 255) / 256, 256>>>(ei, et);
    scan_kernel<<<1, 1024>>>();
    scatter_kernel<<<(N_EDGES + 255) / 256, 256>>>(ei, et);
    invcnt_kernel<<<(2 * N_NODES + 255) / 256, 256>>>();

    const int GEMM_BLOCKS = (N_NODES + 63) / 64;          // 782
    const int GATH_BLOCKS = (N_NODES + 7) / 8;            // 6250 (8 warps/block)

    // ---- layer 1 ----
    gemm_kernel<128, false, false><<<GEMM_BLOCKS, 256>>>(x, root1, W1, b1);
    gather_kernel<true, false><<<GATH_BLOCKS, 256>>>(g1, be1, nullptr);

    // ---- layer 2 ----
    gemm_kernel<64, true, true><<<GEMM_BLOCKS, 256>>>(nullptr, root2, W2, b2);
    gather_kernel<false, true><<<GATH_BLOCKS, 256>>>(g2, be2, out);
}

// round 4
// speedup vs baseline: 1.2851x; 1.2851x over previous
#include <cuda_runtime.h>
#include <cuda_bf16.h>
#include <math.h>

#define N_NODES 50000
#define N_EDGES 800000
#define LN_EPS 1e-5f
#define SCAN_BLOCKS 196            // ceil(50000/256)

// ---------------- scratch (no allocations allowed -> device globals) ----------
__device__ int   g_is64;
__device__ int   g_cursor[N_NODES];
__device__ int   g_rowptr[N_NODES + 1];
__device__ int   g_cntrel[N_NODES * 2];
__device__ int   g_bsum[SCAN_BLOCKS];
__device__ int   g_boff[SCAN_BLOCKS];
__device__ float g_invcnt[N_NODES * 2];
__device__ int   g_epack[N_EDGES];              // (src<<1)|rel, CSR-ordered by dst
__device__ float g_proj1[N_NODES * 128];        // [n][r*64+c]  x@W1[r]
__device__ float g_sel1 [N_NODES * 64];         // x@root1 + b1
__device__ float g_h    [N_NODES * 64];         // layer1 output
__device__ float g_proj2[N_NODES * 128];
__device__ float g_sel2 [N_NODES * 64];

// ---------------- dtype sniff: int64 edge_index has zero high words -----------
__global__ void sniff_kernel(const int* __restrict__ ei32) {
    __shared__ int acc[256];
    int t = threadIdx.x;
    int v = 0;
    for (int i = t; i < 2048; i += 256) v |= ei32[2 * i + 1];
    acc[t] = v;
    __syncthreads();
    for (int off = 128; off; off >>= 1) {
        if (t < off) acc[t] |= acc[t + off];
        __syncthreads();
    }
    if (t == 0) g_is64 = (acc[0] == 0) ? 1 : 0;
}

__device__ __forceinline__ int load_idx(const void* p, int i) {
    return g_is64 ? (int)((const long long*)p)[i] : ((const int*)p)[i];
}

// ---------------- CSR build ---------------------------------------------------
__global__ void zero_kernel() {
    int i = blockIdx.x * blockDim.x + threadIdx.x;
    if (i < N_NODES) g_cursor[i] = 0;
    if (i < 2 * N_NODES) g_cntrel[i] = 0;
}

__global__ void count_kernel(const void* __restrict__ ei,
                             const void* __restrict__ et) {
    int e = blockIdx.x * blockDim.x + threadIdx.x;
    if (e >= N_EDGES) return;
    int d = load_idx(ei, N_EDGES + e);
    int r = load_idx(et, e) & 1;
    d = min(max(d, 0), N_NODES - 1);
    atomicAdd(&g_cntrel[d * 2 + r], 1);
}

__device__ __forceinline__ int node_cnt(int i) {
    return g_cntrel[2 * i] + g_cntrel[2 * i + 1];
}

// phase A: per-block sums of 256 node counts
__global__ void scanA_kernel() {
    __shared__ int ws[8];
    int i = blockIdx.x * 256 + threadIdx.x;
    int v = (i < N_NODES) ? node_cnt(i) : 0;
    int lane = threadIdx.x & 31, w = threadIdx.x >> 5;
#pragma unroll
    for (int off = 16; off; off >>= 1) v += __shfl_xor_sync(~0u, v, off);
    if (lane == 0) ws[w] = v;
    __syncthreads();
    if (threadIdx.x < 8) {
        int s = ws[threadIdx.x];
#pragma unroll
        for (int off = 4; off; off >>= 1) s += __shfl_xor_sync(0xffu, s, off);
        if (threadIdx.x == 0) g_bsum[blockIdx.x] = s;
    }
}

// phase B: exclusive scan of SCAN_BLOCKS partials (1 block)
__global__ void scanB_kernel() {
    __shared__ int ss[256];
    int t = threadIdx.x;
    int v = (t < SCAN_BLOCKS) ? g_bsum[t] : 0;
    ss[t] = v;
    __syncthreads();
    for (int off = 1; off < 256; off <<= 1) {
        int u = (t >= off) ? ss[t - off] : 0;
        __syncthreads();
        ss[t] += u;
        __syncthreads();
    }
    if (t < SCAN_BLOCKS) g_boff[t] = ss[t] - v;   // exclusive
    if (t == 255) g_rowptr[N_NODES] = ss[SCAN_BLOCKS - 1];
}

// phase C: in-block exclusive scan + block offset -> rowptr
__global__ void scanC_kernel() {
    __shared__ int ss[256];
    int t = threadIdx.x;
    int i = blockIdx.x * 256 + t;
    int v = (i < N_NODES) ? node_cnt(i) : 0;
    ss[t] = v;
    __syncthreads();
    for (int off = 1; off < 256; off <<= 1) {
        int u = (t >= off) ? ss[t - off] : 0;
        __syncthreads();
        ss[t] += u;
        __syncthreads();
    }
    if (i < N_NODES) g_rowptr[i] = g_boff[blockIdx.x] + ss[t] - v;
}

__global__ void scatter_kernel(const void* __restrict__ ei,
                               const void* __restrict__ et) {
    int e = blockIdx.x * blockDim.x + threadIdx.x;
    if (e >= N_EDGES) return;
    int s = load_idx(ei, e);
    int d = load_idx(ei, N_EDGES + e);
    int r = load_idx(et, e) & 1;
    s = min(max(s, 0), N_NODES - 1);
    d = min(max(d, 0), N_NODES - 1);
    int pos = g_rowptr[d] + atomicAdd(&g_cursor[d], 1);
    if (pos >= 0 && pos < N_EDGES) g_epack[pos] = (s << 1) | r;
}

__global__ void invcnt_kernel() {
    int i = blockIdx.x * blockDim.x + threadIdx.x;
    if (i < 2 * N_NODES)
        g_invcnt[i] = 1.0f / fmaxf((float)g_cntrel[i], 1.0f);
}

// ---------------- fused GEMM: [N,KD] @ [KD,192] -> sel[N,64], proj[N,128] -----
// cols 0..63 = root (+bias), 64..127 = W[0], 128..191 = W[1]
// 64-row x 192-col block, 256 threads, K staged in 32-slices (static smem ~32KB).
// Packed fma.rn.f32x2 accumulators (FFMA2) for 2x fp32 rate.
template <int KD, bool USE_H, bool L2OUT>
__global__ void __launch_bounds__(256)
gemm_kernel(const float* __restrict__ Xin, const float* __restrict__ root,
            const float* __restrict__ W, const float* __restrict__ bias) {
    __shared__ float Ws[32 * 192];
    __shared__ float Xs[64 * 33];
    const float* X = USE_H ? g_h : Xin;
    float* sel  = L2OUT ? g_sel2  : g_sel1;
    float* proj = L2OUT ? g_proj2 : g_proj1;

    const int tid = threadIdx.x;
    const int row0 = blockIdx.x * 64;
    const int tx = tid & 15;     // cols: 2*tx + 32*j (+1)
    const int ty = tid >> 4;     // rows: ty*4 .. ty*4+3

    unsigned long long acc[4][6];
#pragma unroll
    for (int i = 0; i < 4; i++)
#pragma unroll
        for (int j = 0; j < 6; j++) acc[i][j] = 0ull;

    for (int k0 = 0; k0 < KD; k0 += 32) {
        __syncthreads();
        for (int idx = tid; idx < 32 * 192; idx += 256) {
            int kk = idx / 192, cc = idx % 192;
            int k = k0 + kk;
            float w;
            if (cc < 64) w = root[k * 64 + cc];
            else         w = W[(((cc >> 6) - 1) * KD + k) * 64 + (cc & 63)];
            Ws[idx] = w;
        }
        for (int idx = tid; idx < 64 * 32; idx += 256) {
            int rw = idx >> 5, kk = idx & 31;
            int n = row0 + rw;
            Xs[rw * 33 + kk] = (n < N_NODES) ? X[n * KD + k0 + kk] : 0.0f;
        }
        __syncthreads();

#pragma unroll 4
        for (int kk = 0; kk < 32; kk++) {
            unsigned long long xv[4];
#pragma unroll
            for (int i = 0; i < 4; i++) {
                float xr = Xs[(ty * 4 + i) * 33 + kk];
                asm("mov.b64 %0, {%1, %1};" : "=l"(xv[i]) : "f"(xr));
            }
#pragma unroll
            for (int j = 0; j < 6; j++) {
                unsigned long long wv =
                    *reinterpret_cast<const unsigned long long*>(&Ws[kk * 192 + 2 * tx + 32 * j]);
#pragma unroll
                for (int i = 0; i < 4; i++) {
                    asm("fma.rn.f32x2 %0, %1, %2, %0;"
                        : "+l"(acc[i][j]) : "l"(xv[i]), "l"(wv));
                }
            }
        }
    }

#pragma unroll
    for (int i = 0; i < 4; i++) {
        int n = row0 + ty * 4 + i;
        if (n < N_NODES) {
#pragma unroll
            for (int j = 0; j < 6; j++) {
                int cc = 2 * tx + 32 * j;
                float lo, hi;
                asm("mov.b64 {%0, %1}, %2;" : "=f"(lo), "=f"(hi) : "l"(acc[i][j]));
                if (cc < 64) {
                    float2 o; o.x = lo + bias[cc]; o.y = hi + bias[cc + 1];
                    *reinterpret_cast<float2*>(&sel[n * 64 + cc]) = o;
                } else {
                    float2 o; o.x = lo; o.y = hi;
                    *reinterpret_cast<float2*>(&proj[n * 128 + (cc - 64)]) = o;
                }
            }
        }
    }
}

// ---------------- gather + mean + LayerNorm (+GELU) ---------------------------
// One warp per node; lane owns cols {lane, lane+32}.
template <bool DO_GELU, bool L2>
__global__ void gather_kernel(const float* __restrict__ gamma,
                              const float* __restrict__ beta,
                              float* __restrict__ outp) {
    const float* sel  = L2 ? g_sel2  : g_sel1;
    const float* proj = L2 ? g_proj2 : g_proj1;
    float* out = L2 ? outp : g_h;

    int warp = (blockIdx.x * blockDim.x + threadIdx.x) >> 5;
    int lane = threadIdx.x & 31;
    if (warp >= N_NODES) return;
    const int i = warp;
    int beg = g_rowptr[i], end = g_rowptr[i + 1];

    float a00 = 0.f, a01 = 0.f, a10 = 0.f, a11 = 0.f;
    int t = beg;
    for (; t + 4 <= end; t += 4) {
        int e0 = g_epack[t], e1 = g_epack[t + 1], e2 = g_epack[t + 2], e3 = g_epack[t + 3];
        const float* p0 = proj + (e0 >> 1) * 128 + ((e0 & 1) << 6);
        const float* p1 = proj + (e1 >> 1) * 128 + ((e1 & 1) << 6);
        const float* p2 = proj + (e2 >> 1) * 128 + ((e2 & 1) << 6);
        const float* p3 = proj + (e3 >> 1) * 128 + ((e3 & 1) << 6);
        float v00 = p0[lane], v01 = p0[lane + 32];
        float v10 = p1[lane], v11 = p1[lane + 32];
        float v20 = p2[lane], v21 = p2[lane + 32];
        float v30 = p3[lane], v31 = p3[lane + 32];
        if (e0 & 1) { a10 += v00; a11 += v01; } else { a00 += v00; a01 += v01; }
        if (e1 & 1) { a10 += v10; a11 += v11; } else { a00 += v10; a01 += v11; }
        if (e2 & 1) { a10 += v20; a11 += v21; } else { a00 += v20; a01 += v21; }
        if (e3 & 1) { a10 += v30; a11 += v31; } else { a00 += v30; a01 += v31; }
    }
    for (; t < end; t++) {
        int e0 = g_epack[t];
        const float* p0 = proj + (e0 >> 1) * 128 + ((e0 & 1) << 6);
        float v00 = p0[lane], v01 = p0[lane + 32];
        if (e0 & 1) { a10 += v00; a11 += v01; } else { a00 += v00; a01 += v01; }
    }

    float ic0 = g_invcnt[2 * i], ic1 = g_invcnt[2 * i + 1];
    float v0 = sel[i * 64 + lane]      + a00 * ic0 + a10 * ic1;
    float v1 = sel[i * 64 + lane + 32] + a01 * ic0 + a11 * ic1;

    float s  = v0 + v1;
    float sq = v0 * v0 + v1 * v1;
#pragma unroll
    for (int off = 16; off; off >>= 1) {
        s  += __shfl_xor_sync(0xffffffffu, s,  off);
        sq += __shfl_xor_sync(0xffffffffu, sq, off);
    }
    float mean = s * (1.0f / 64.0f);
    float var  = sq * (1.0f / 64.0f) - mean * mean;
    float inv  = rsqrtf(var + LN_EPS);
    v0 = (v0 - mean) * inv * gamma[lane]      + beta[lane];
    v1 = (v1 - mean) * inv * gamma[lane + 32] + beta[lane + 32];

    if (DO_GELU) {
        v0 = 0.5f * v0 * (1.0f + erff(v0 * 0.70710678118654752440f));
        v1 = 0.5f * v1 * (1.0f + erff(v1 * 0.70710678118654752440f));
    }
    out[i * 64 + lane]      = v0;
    out[i * 64 + lane + 32] = v1;
}

// ---------------- launcher ----------------------------------------------------
extern "C" void kernel_launch(void* const* d_in, const int* in_sizes, int n_in,
                              void* d_out, int out_size) {
    const float* x     = (const float*)d_in[0];
    const void*  ei    = d_in[1];
    const void*  et    = d_in[2];
    const float* W1    = (const float*)d_in[3];
    const float* root1 = (const float*)d_in[4];
    const float* b1    = (const float*)d_in[5];
    const float* g1    = (const float*)d_in[6];
    const float* be1   = (const float*)d_in[7];
    const float* W2    = (const float*)d_in[8];
    const float* root2 = (const float*)d_in[9];
    const float* b2    = (const float*)d_in[10];
    const float* g2    = (const float*)d_in[11];
    const float* be2   = (const float*)d_in[12];
    float* out = (float*)d_out;

    // ---- dtype sniff + CSR build (by dst) ----
    sniff_kernel<<<1, 256>>>((const int*)ei);
    zero_kernel<<<(2 * N_NODES + 255) / 256, 256>>>();
    count_kernel<<<(N_EDGES + 255) / 256, 256>>>(ei, et);
    scanA_kernel<<<SCAN_BLOCKS, 256>>>();
    scanB_kernel<<<1, 256>>>();
    scanC_kernel<<<SCAN_BLOCKS, 256>>>();
    scatter_kernel<<<(N_EDGES + 255) / 256, 256>>>(ei, et);
    invcnt_kernel<<<(2 * N_NODES + 255) / 256, 256>>>();

    const int GEMM_BLOCKS = (N_NODES + 63) / 64;          // 782
    const int GATH_BLOCKS = (N_NODES + 7) / 8;            // 6250 (8 warps/block)

    // ---- layer 1 ----
    gemm_kernel<128, false, false><<<GEMM_BLOCKS, 256>>>(x, root1, W1, b1);
    gather_kernel<true, false><<<GATH_BLOCKS, 256>>>(g1, be1, nullptr);

    // ---- layer 2 ----
    gemm_kernel<64, true, true><<<GEMM_BLOCKS, 256>>>(nullptr, root2, W2, b2);
    gather_kernel<false, true><<<GATH_BLOCKS, 256>>>(g2, be2, out);
}

// round 5
// speedup vs baseline: 1.4304x; 1.1131x over previous
#include <cuda_runtime.h>
#include <cuda_bf16.h>
#include <math.h>

#define N_NODES 50000
#define N_EDGES 800000
#define LN_EPS 1e-5f
#define SCAN_BLOCKS 196            // ceil(50000/256)

// ---------------- scratch (no allocations allowed -> device globals) ----------
__device__ int   g_is64;
__device__ int   g_cursor[N_NODES];
__device__ int   g_rowptr[N_NODES + 1];
__device__ int   g_cntrel[N_NODES * 2];
__device__ int   g_bsum[SCAN_BLOCKS];
__device__ int   g_boff[SCAN_BLOCKS];
__device__ float g_invcnt[N_NODES * 2];
__device__ int   g_epack[N_EDGES];              // (src<<1)|rel, CSR-ordered by dst
__device__ float g_proj1[N_NODES * 128];        // [n][r*64+c]  x@W1[r]
__device__ float g_sel1 [N_NODES * 64];         // x@root1 + b1
__device__ float g_h    [N_NODES * 64];         // layer1 output
__device__ float g_proj2[N_NODES * 128];
__device__ float g_sel2 [N_NODES * 64];

// ---------------- zero + dtype sniff (block 0 sniffs) --------------------------
// int64 edge_index has all-zero high 32-bit words (values < 50000).
__global__ void zero_sniff_kernel(const int* __restrict__ ei32) {
    int i = blockIdx.x * blockDim.x + threadIdx.x;
    if (i < N_NODES) g_cursor[i] = 0;
    if (i < 2 * N_NODES) g_cntrel[i] = 0;
    if (blockIdx.x == 0) {
        __shared__ int acc[256];
        int t = threadIdx.x;
        int v = 0;
        for (int k = t; k < 2048; k += 256) v |= ei32[2 * k + 1];
        acc[t] = v;
        __syncthreads();
        for (int off = 128; off; off >>= 1) {
            if (t < off) acc[t] |= acc[t + off];
            __syncthreads();
        }
        if (t == 0) g_is64 = (acc[0] == 0) ? 1 : 0;
    }
}

__device__ __forceinline__ int load_idx(const void* p, int i) {
    return g_is64 ? (int)((const long long*)p)[i] : ((const int*)p)[i];
}

// ---------------- CSR build ---------------------------------------------------
__global__ void count_kernel(const void* __restrict__ ei,
                             const void* __restrict__ et) {
    int e0 = (blockIdx.x * blockDim.x + threadIdx.x) * 2;
#pragma unroll
    for (int u = 0; u < 2; u++) {
        int e = e0 + u;
        if (e >= N_EDGES) return;
        int d = load_idx(ei, N_EDGES + e);
        int r = load_idx(et, e) & 1;
        d = min(max(d, 0), N_NODES - 1);
        atomicAdd(&g_cntrel[d * 2 + r], 1);
    }
}

__device__ __forceinline__ int node_cnt(int i) {
    return g_cntrel[2 * i] + g_cntrel[2 * i + 1];
}

// phase A: per-block sums of 256 node counts
__global__ void scanA_kernel() {
    __shared__ int ws[8];
    int i = blockIdx.x * 256 + threadIdx.x;
    int v = (i < N_NODES) ? node_cnt(i) : 0;
    int lane = threadIdx.x & 31, w = threadIdx.x >> 5;
#pragma unroll
    for (int off = 16; off; off >>= 1) v += __shfl_xor_sync(~0u, v, off);
    if (lane == 0) ws[w] = v;
    __syncthreads();
    if (threadIdx.x < 8) {
        int s = ws[threadIdx.x];
#pragma unroll
        for (int off = 4; off; off >>= 1) s += __shfl_xor_sync(0xffu, s, off);
        if (threadIdx.x == 0) g_bsum[blockIdx.x] = s;
    }
}

// phase B: exclusive scan of SCAN_BLOCKS partials (1 block)
__global__ void scanB_kernel() {
    __shared__ int ss[256];
    int t = threadIdx.x;
    int v = (t < SCAN_BLOCKS) ? g_bsum[t] : 0;
    ss[t] = v;
    __syncthreads();
    for (int off = 1; off < 256; off <<= 1) {
        int u = (t >= off) ? ss[t - off] : 0;
        __syncthreads();
        ss[t] += u;
        __syncthreads();
    }
    if (t < SCAN_BLOCKS) g_boff[t] = ss[t] - v;   // exclusive
    if (t == 255) g_rowptr[N_NODES] = ss[SCAN_BLOCKS - 1];
}

// phase C: in-block exclusive scan + block offset -> rowptr; also invcnt
__global__ void scanC_kernel() {
    __shared__ int ss[256];
    int t = threadIdx.x;
    int i = blockIdx.x * 256 + t;
    int v = (i < N_NODES) ? node_cnt(i) : 0;
    ss[t] = v;
    __syncthreads();
    for (int off = 1; off < 256; off <<= 1) {
        int u = (t >= off) ? ss[t - off] : 0;
        __syncthreads();
        ss[t] += u;
        __syncthreads();
    }
    if (i < N_NODES) {
        g_rowptr[i] = g_boff[blockIdx.x] + ss[t] - v;
        g_invcnt[2 * i]     = 1.0f / fmaxf((float)g_cntrel[2 * i], 1.0f);
        g_invcnt[2 * i + 1] = 1.0f / fmaxf((float)g_cntrel[2 * i + 1], 1.0f);
    }
}

__global__ void scatter_kernel(const void* __restrict__ ei,
                               const void* __restrict__ et) {
    int e0 = (blockIdx.x * blockDim.x + threadIdx.x) * 2;
#pragma unroll
    for (int u = 0; u < 2; u++) {
        int e = e0 + u;
        if (e >= N_EDGES) return;
        int s = load_idx(ei, e);
        int d = load_idx(ei, N_EDGES + e);
        int r = load_idx(et, e) & 1;
        s = min(max(s, 0), N_NODES - 1);
        d = min(max(d, 0), N_NODES - 1);
        int pos = g_rowptr[d] + atomicAdd(&g_cursor[d], 1);
        if (pos >= 0 && pos < N_EDGES) g_epack[pos] = (s << 1) | r;
    }
}

// ---------------- fused GEMM: [N,KD] @ [KD,192] -> sel[N,64], proj[N,128] -----
// cols 0..63 = root (+bias), 64..127 = W[0], 128..191 = W[1]
// 64-row x 192-col block, 256 threads, K staged in 32-slices.
// Packed fma.rn.f32x2 accumulators (FFMA2) for 2x fp32 rate.
template <int KD, bool USE_H, bool L2OUT>
__global__ void __launch_bounds__(256)
gemm_kernel(const float* __restrict__ Xin, const float* __restrict__ root,
            const float* __restrict__ W, const float* __restrict__ bias) {
    __shared__ float Ws[32 * 192];
    __shared__ float Xs[64 * 33];
    const float* X = USE_H ? g_h : Xin;
    float* sel  = L2OUT ? g_sel2  : g_sel1;
    float* proj = L2OUT ? g_proj2 : g_proj1;

    const int tid = threadIdx.x;
    const int row0 = blockIdx.x * 64;
    const int tx = tid & 15;     // cols: 2*tx + 32*j (+1)
    const int ty = tid >> 4;     // rows: ty*4 .. ty*4+3

    unsigned long long acc[4][6];
#pragma unroll
    for (int i = 0; i < 4; i++)
#pragma unroll
        for (int j = 0; j < 6; j++) acc[i][j] = 0ull;

    for (int k0 = 0; k0 < KD; k0 += 32) {
        __syncthreads();
        for (int idx = tid; idx < 32 * 192; idx += 256) {
            int kk = idx / 192, cc = idx % 192;
            int k = k0 + kk;
            float w;
            if (cc < 64) w = root[k * 64 + cc];
            else         w = W[(((cc >> 6) - 1) * KD + k) * 64 + (cc & 63)];
            Ws[idx] = w;
        }
        for (int idx = tid; idx < 64 * 32; idx += 256) {
            int rw = idx >> 5, kk = idx & 31;
            int n = row0 + rw;
            Xs[rw * 33 + kk] = (n < N_NODES) ? X[n * KD + k0 + kk] : 0.0f;
        }
        __syncthreads();

#pragma unroll 4
        for (int kk = 0; kk < 32; kk++) {
            unsigned long long xv[4];
#pragma unroll
            for (int i = 0; i < 4; i++) {
                float xr = Xs[(ty * 4 + i) * 33 + kk];
                asm("mov.b64 %0, {%1, %1};" : "=l"(xv[i]) : "f"(xr));
            }
#pragma unroll
            for (int j = 0; j < 6; j++) {
                unsigned long long wv =
                    *reinterpret_cast<const unsigned long long*>(&Ws[kk * 192 + 2 * tx + 32 * j]);
#pragma unroll
                for (int i = 0; i < 4; i++) {
                    asm("fma.rn.f32x2 %0, %1, %2, %0;"
                        : "+l"(acc[i][j]) : "l"(xv[i]), "l"(wv));
                }
            }
        }
    }

#pragma unroll
    for (int i = 0; i < 4; i++) {
        int n = row0 + ty * 4 + i;
        if (n < N_NODES) {
#pragma unroll
            for (int j = 0; j < 6; j++) {
                int cc = 2 * tx + 32 * j;
                float lo, hi;
                asm("mov.b64 {%0, %1}, %2;" : "=f"(lo), "=f"(hi) : "l"(acc[i][j]));
                if (cc < 64) {
                    float2 o; o.x = lo + bias[cc]; o.y = hi + bias[cc + 1];
                    *reinterpret_cast<float2*>(&sel[n * 64 + cc]) = o;
                } else {
                    float2 o; o.x = lo; o.y = hi;
                    *reinterpret_cast<float2*>(&proj[n * 128 + (cc - 64)]) = o;
                }
            }
        }
    }
}

// ---------------- gather + mean + LayerNorm (+GELU) ---------------------------
// One warp per node; lane owns cols {lane, lane+32}.
template <bool DO_GELU, bool L2>
__global__ void gather_kernel(const float* __restrict__ gamma,
                              const float* __restrict__ beta,
                              float* __restrict__ outp) {
    const float* sel  = L2 ? g_sel2  : g_sel1;
    const float* proj = L2 ? g_proj2 : g_proj1;
    float* out = L2 ? outp : g_h;

    int warp = (blockIdx.x * blockDim.x + threadIdx.x) >> 5;
    int lane = threadIdx.x & 31;
    if (warp >= N_NODES) return;
    const int i = warp;
    int beg = g_rowptr[i], end = g_rowptr[i + 1];

    float a00 = 0.f, a01 = 0.f, a10 = 0.f, a11 = 0.f;
    int t = beg;
    for (; t + 4 <= end; t += 4) {
        int e0 = g_epack[t], e1 = g_epack[t + 1], e2 = g_epack[t + 2], e3 = g_epack[t + 3];
        const float* p0 = proj + (e0 >> 1) * 128 + ((e0 & 1) << 6);
        const float* p1 = proj + (e1 >> 1) * 128 + ((e1 & 1) << 6);
        const float* p2 = proj + (e2 >> 1) * 128 + ((e2 & 1) << 6);
        const float* p3 = proj + (e3 >> 1) * 128 + ((e3 & 1) << 6);
        float v00 = p0[lane], v01 = p0[lane + 32];
        float v10 = p1[lane], v11 = p1[lane + 32];
        float v20 = p2[lane], v21 = p2[lane + 32];
        float v30 = p3[lane], v31 = p3[lane + 32];
        if (e0 & 1) { a10 += v00; a11 += v01; } else { a00 += v00; a01 += v01; }
        if (e1 & 1) { a10 += v10; a11 += v11; } else { a00 += v10; a01 += v11; }
        if (e2 & 1) { a10 += v20; a11 += v21; } else { a00 += v20; a01 += v21; }
        if (e3 & 1) { a10 += v30; a11 += v31; } else { a00 += v30; a01 += v31; }
    }
    for (; t < end; t++) {
        int e0 = g_epack[t];
        const float* p0 = proj + (e0 >> 1) * 128 + ((e0 & 1) << 6);
        float v00 = p0[lane], v01 = p0[lane + 32];
        if (e0 & 1) { a10 += v00; a11 += v01; } else { a00 += v00; a01 += v01; }
    }

    float ic0 = g_invcnt[2 * i], ic1 = g_invcnt[2 * i + 1];
    float v0 = sel[i * 64 + lane]      + a00 * ic0 + a10 * ic1;
    float v1 = sel[i * 64 + lane + 32] + a01 * ic0 + a11 * ic1;

    float s  = v0 + v1;
    float sq = v0 * v0 + v1 * v1;
#pragma unroll
    for (int off = 16; off; off >>= 1) {
        s  += __shfl_xor_sync(0xffffffffu, s,  off);
        sq += __shfl_xor_sync(0xffffffffu, sq, off);
    }
    float mean = s * (1.0f / 64.0f);
    float var  = sq * (1.0f / 64.0f) - mean * mean;
    float inv  = rsqrtf(var + LN_EPS);
    v0 = (v0 - mean) * inv * gamma[lane]      + beta[lane];
    v1 = (v1 - mean) * inv * gamma[lane + 32] + beta[lane + 32];

    if (DO_GELU) {
        v0 = 0.5f * v0 * (1.0f + erff(v0 * 0.70710678118654752440f));
        v1 = 0.5f * v1 * (1.0f + erff(v1 * 0.70710678118654752440f));
    }
    out[i * 64 + lane]      = v0;
    out[i * 64 + lane + 32] = v1;
}

// ---------------- launcher ----------------------------------------------------
extern "C" void kernel_launch(void* const* d_in, const int* in_sizes, int n_in,
                              void* d_out, int out_size) {
    const float* x     = (const float*)d_in[0];
    const void*  ei    = d_in[1];
    const void*  et    = d_in[2];
    const float* W1    = (const float*)d_in[3];
    const float* root1 = (const float*)d_in[4];
    const float* b1    = (const float*)d_in[5];
    const float* g1    = (const float*)d_in[6];
    const float* be1   = (const float*)d_in[7];
    const float* W2    = (const float*)d_in[8];
    const float* root2 = (const float*)d_in[9];
    const float* b2    = (const float*)d_in[10];
    const float* g2    = (const float*)d_in[11];
    const float* be2   = (const float*)d_in[12];
    float* out = (float*)d_out;

    // one-time stream/event resources (host-side only; work per call is identical)
    static cudaStream_t s_aux = nullptr;
    static cudaEvent_t  ev_fork = nullptr, ev_join = nullptr;
    if (s_aux == nullptr) {
        cudaStreamCreateWithFlags(&s_aux, cudaStreamNonBlocking);
        cudaEventCreateWithFlags(&ev_fork, cudaEventDisableTiming);
        cudaEventCreateWithFlags(&ev_join, cudaEventDisableTiming);
    }

    const int GEMM_BLOCKS = (N_NODES + 63) / 64;          // 782
    const int GATH_BLOCKS = (N_NODES + 7) / 8;            // 6250 (8 warps/block)
    const int EDGE_BLOCKS = (N_EDGES / 2 + 255) / 256;    // 1563

    // ---- fork: CSR build chain on aux stream, gemm1 on main stream ----
    cudaEventRecord(ev_fork, 0);
    cudaStreamWaitEvent(s_aux, ev_fork, 0);

    zero_sniff_kernel<<<(2 * N_NODES + 255) / 256, 256, 0, s_aux>>>((const int*)ei);
    count_kernel<<<EDGE_BLOCKS, 256, 0, s_aux>>>(ei, et);
    scanA_kernel<<<SCAN_BLOCKS, 256, 0, s_aux>>>();
    scanB_kernel<<<1, 256, 0, s_aux>>>();
    scanC_kernel<<<SCAN_BLOCKS, 256, 0, s_aux>>>();
    scatter_kernel<<<EDGE_BLOCKS, 256, 0, s_aux>>>(ei, et);

    gemm_kernel<128, false, false><<<GEMM_BLOCKS, 256>>>(x, root1, W1, b1);

    // ---- join ----
    cudaEventRecord(ev_join, s_aux);
    cudaStreamWaitEvent(0, ev_join, 0);

    // ---- rest of the pipeline (serial dependencies) ----
    gather_kernel<true, false><<<GATH_BLOCKS, 256>>>(g1, be1, nullptr);
    gemm_kernel<64, true, true><<<GEMM_BLOCKS, 256>>>(nullptr, root2, W2, b2);
    gather_kernel<false, true><<<GATH_BLOCKS, 256>>>(g2, be2, out);
}